// round 3
// baseline (speedup 1.0000x reference)
#include <cuda_runtime.h>
#include <cstdint>

// Codec_35785667510396 — fused autoregressive PixelPred + RMSE + dual histograms.
// x: [16,3,1024,1024] f32. Per 4x4 block, 16 sequential tiny MLPs (15->12->12->12->1).
// Outputs: [loss1, invCR0, invCR1].
//
// Strategy: 1 thread = 2 blocks packed into f32x2 lanes (FFMA2). Weights in smem,
// W0 stored with a zero row inserted at position k so the layer-0 dot is a dense
// 16x12 product over a register array v[16] (x pixels progressively replaced by errs).

typedef unsigned long long u64;

#define TPB 256
#define NB 2
#define BLOCKS_PER_CTA (TPB * NB)   // 512
#define CHUNKS (65536 / BLOCKS_PER_CTA) // 128
#define NBC 48

__device__ double g_sumsq;
__device__ unsigned int g_hist_x[NBC * 256];
__device__ unsigned int g_hist_d[NBC * 256];

__device__ __forceinline__ u64 pack2(float lo, float hi) {
    u64 r; asm("mov.b64 %0, {%1, %2};" : "=l"(r) : "f"(lo), "f"(hi)); return r;
}
__device__ __forceinline__ float2 unpack2(u64 v) {
    float2 f; asm("mov.b64 {%0, %1}, %2;" : "=f"(f.x), "=f"(f.y) : "l"(v)); return f;
}
__device__ __forceinline__ u64 ffma2(u64 a, u64 b, u64 c) {
    u64 d; asm("fma.rn.f32x2 %0, %1, %2, %3;" : "=l"(d) : "l"(a), "l"(b), "l"(c)); return d;
}
__device__ __forceinline__ u64 dup2(float w) { return pack2(w, w); }

__device__ __forceinline__ u64 leaky2(u64 a) {
    float2 f = unpack2(a);
    f.x = (f.x >= 0.0f) ? f.x : 0.01f * f.x;
    f.y = (f.y >= 0.0f) ? f.y : 0.01f * f.y;
    return pack2(f.x, f.y);
}

__device__ __forceinline__ int binof(float v) {
    int t = (int)floorf((v + 1.0f) * 128.0f);
    t = max(t, 0); t = min(t, 255);
    return t;
}

// delta = x - clip(pred,-1,1); fmod(delta+1,2)-1 with t in [-1,3]
__device__ __forceinline__ float wrapdelta(float xv, float pred) {
    float p = fminf(fmaxf(pred, -1.0f), 1.0f);
    float t = (xv - p) + 1.0f;
    t = (t >= 2.0f) ? (t - 2.0f) : t;
    return t - 1.0f;
}

struct __align__(16) Smem {
    float W0p[16 * 16 * 12];  // padded: zero row at j==k
    float b0[16 * 12];
    float W1[16 * 144];
    float b1[16 * 12];
    float W2[16 * 144];
    float b2[16 * 12];
    float W3[16 * 12];
    float b3[16];
    unsigned int hx[256];
    unsigned int hd[256];
    float warpsums[8];
};

__global__ void __launch_bounds__(TPB, 2) codec_main(
    const float* __restrict__ x,
    const float* __restrict__ W0, const float* __restrict__ b0,
    const float* __restrict__ W1, const float* __restrict__ b1,
    const float* __restrict__ W2, const float* __restrict__ b2,
    const float* __restrict__ W3, const float* __restrict__ b3)
{
    __shared__ Smem s;
    const int tid = threadIdx.x;
    const int bc = blockIdx.x / CHUNKS;     // 0..47  (= b*3 + c)
    const int chunk = blockIdx.x % CHUNKS;
    const int c = bc % 3;

    // ---- load weights into smem (W0 with inserted zero row) ----
    for (int idx = tid; idx < 16 * 16 * 12; idx += TPB) {
        int k = idx / 192; int r = idx % 192; int j = r / 12; int o = r % 12;
        float w = 0.0f;
        if (j != k) {
            int i = j - (j > k);
            w = W0[((c * 16 + k) * 15 + i) * 12 + o];
        }
        s.W0p[idx] = w;
    }
    for (int idx = tid; idx < 192; idx += TPB) {
        s.b0[idx] = b0[c * 192 + idx];
        s.b1[idx] = b1[c * 192 + idx];
        s.b2[idx] = b2[c * 192 + idx];
        s.W3[idx] = W3[c * 192 + idx];
    }
    for (int idx = tid; idx < 2304; idx += TPB) {
        s.W1[idx] = W1[c * 2304 + idx];
        s.W2[idx] = W2[c * 2304 + idx];
    }
    if (tid < 16) s.b3[tid] = b3[c * 16 + tid];
    s.hx[tid] = 0;
    s.hd[tid] = 0;
    __syncthreads();

    // ---- load 2 blocks of 16 pixels, packed ----
    const int n0 = chunk * BLOCKS_PER_CTA + tid;   // block A
    const int n1 = n0 + TPB;                       // block B
    const float* xb = x + (size_t)bc * (1024 * 1024);
    const float* pA = xb + ((n0 >> 8) * 4096) + ((n0 & 255) * 4);
    const float* pB = xb + ((n1 >> 8) * 4096) + ((n1 & 255) * 4);

    u64 v[16];
#pragma unroll
    for (int r = 0; r < 4; r++) {
        float4 a  = *(const float4*)(pA + r * 1024);
        float4 bb = *(const float4*)(pB + r * 1024);
        v[r * 4 + 0] = pack2(a.x, bb.x);
        v[r * 4 + 1] = pack2(a.y, bb.y);
        v[r * 4 + 2] = pack2(a.z, bb.z);
        v[r * 4 + 3] = pack2(a.w, bb.w);
    }

    // ---- histogram of raw x ----
#pragma unroll
    for (int j = 0; j < 16; j++) {
        float2 f = unpack2(v[j]);
        atomicAdd(&s.hx[binof(f.x)], 1u);
        atomicAdd(&s.hx[binof(f.y)], 1u);
    }

    // ---- autoregressive 16-step MLP chain ----
    float sq = 0.0f;
#pragma unroll 1
    for (int k = 0; k < 16; k++) {
        const float* W0k = s.W0p + k * 192;
        const float* b0k = s.b0 + k * 12;
        const float* W1k = s.W1 + k * 144;
        const float* b1k = s.b1 + k * 12;
        const float* W2k = s.W2 + k * 144;
        const float* b2k = s.b2 + k * 12;
        const float* W3k = s.W3 + k * 12;

        u64 acc[12];
        u64 h[12];

        // layer 0: 16 (padded) x 12
#pragma unroll
        for (int o = 0; o < 12; o++) acc[o] = dup2(b0k[o]);
#pragma unroll
        for (int j = 0; j < 16; j++) {
            u64 vj = v[j];
            const float4* wp = (const float4*)(W0k + j * 12);
#pragma unroll
            for (int q = 0; q < 3; q++) {
                float4 w = wp[q];
                acc[q * 4 + 0] = ffma2(dup2(w.x), vj, acc[q * 4 + 0]);
                acc[q * 4 + 1] = ffma2(dup2(w.y), vj, acc[q * 4 + 1]);
                acc[q * 4 + 2] = ffma2(dup2(w.z), vj, acc[q * 4 + 2]);
                acc[q * 4 + 3] = ffma2(dup2(w.w), vj, acc[q * 4 + 3]);
            }
        }
#pragma unroll
        for (int o = 0; o < 12; o++) h[o] = leaky2(acc[o]);

        // layer 1: 12 x 12
#pragma unroll
        for (int o = 0; o < 12; o++) acc[o] = dup2(b1k[o]);
#pragma unroll
        for (int i = 0; i < 12; i++) {
            u64 hi_ = h[i];
            const float4* wp = (const float4*)(W1k + i * 12);
#pragma unroll
            for (int q = 0; q < 3; q++) {
                float4 w = wp[q];
                acc[q * 4 + 0] = ffma2(dup2(w.x), hi_, acc[q * 4 + 0]);
                acc[q * 4 + 1] = ffma2(dup2(w.y), hi_, acc[q * 4 + 1]);
                acc[q * 4 + 2] = ffma2(dup2(w.z), hi_, acc[q * 4 + 2]);
                acc[q * 4 + 3] = ffma2(dup2(w.w), hi_, acc[q * 4 + 3]);
            }
        }
#pragma unroll
        for (int o = 0; o < 12; o++) h[o] = leaky2(acc[o]);

        // layer 2: 12 x 12
#pragma unroll
        for (int o = 0; o < 12; o++) acc[o] = dup2(b2k[o]);
#pragma unroll
        for (int i = 0; i < 12; i++) {
            u64 hi_ = h[i];
            const float4* wp = (const float4*)(W2k + i * 12);
#pragma unroll
            for (int q = 0; q < 3; q++) {
                float4 w = wp[q];
                acc[q * 4 + 0] = ffma2(dup2(w.x), hi_, acc[q * 4 + 0]);
                acc[q * 4 + 1] = ffma2(dup2(w.y), hi_, acc[q * 4 + 1]);
                acc[q * 4 + 2] = ffma2(dup2(w.z), hi_, acc[q * 4 + 2]);
                acc[q * 4 + 3] = ffma2(dup2(w.w), hi_, acc[q * 4 + 3]);
            }
        }
#pragma unroll
        for (int o = 0; o < 12; o++) h[o] = leaky2(acc[o]);

        // layer 3: 12 -> 1
        u64 acc3 = dup2(s.b3[k]);
        const float4* wp3 = (const float4*)W3k;
#pragma unroll
        for (int q = 0; q < 3; q++) {
            float4 w = wp3[q];
            acc3 = ffma2(dup2(w.x), h[q * 4 + 0], acc3);
            acc3 = ffma2(dup2(w.y), h[q * 4 + 1], acc3);
            acc3 = ffma2(dup2(w.z), h[q * 4 + 2], acc3);
            acc3 = ffma2(dup2(w.w), h[q * 4 + 3], acc3);
        }

        // read x_k (predicated select, no dynamic index)
        u64 xk = v[0];
#pragma unroll
        for (int j = 1; j < 16; j++) if (j == k) xk = v[j];

        float2 p  = unpack2(acc3);
        float2 xv = unpack2(xk);
        float e0 = wrapdelta(xv.x, p.x);
        float e1 = wrapdelta(xv.y, p.y);
        sq += e0 * e0 + e1 * e1;
        atomicAdd(&s.hd[binof(e0)], 1u);
        atomicAdd(&s.hd[binof(e1)], 1u);

        u64 ev = pack2(e0, e1);
#pragma unroll
        for (int j = 0; j < 16; j++) if (j == k) v[j] = ev;
    }

    // ---- reductions ----
#pragma unroll
    for (int off = 16; off; off >>= 1) sq += __shfl_xor_sync(0xFFFFFFFFu, sq, off);
    if ((tid & 31) == 0) s.warpsums[tid >> 5] = sq;
    __syncthreads();
    if (tid == 0) {
        float t = 0.0f;
#pragma unroll
        for (int w = 0; w < 8; w++) t += s.warpsums[w];
        atomicAdd(&g_sumsq, (double)t);
    }
    atomicAdd(&g_hist_x[bc * 256 + tid], s.hx[tid]);
    atomicAdd(&g_hist_d[bc * 256 + tid], s.hd[tid]);
}

__global__ void codec_zero() {
    int t = blockIdx.x * blockDim.x + threadIdx.x;
    if (t < NBC * 256) { g_hist_x[t] = 0; g_hist_d[t] = 0; }
    if (t == 0) g_sumsq = 0.0;
}

__global__ void codec_final(float* __restrict__ out) {
    __shared__ double red[256];
    const int t = threadIdx.x;
    const float invres = 1.0f / 1048576.0f;
    double ex = 0.0, ed = 0.0;
    for (int i = t; i < NBC * 256; i += 256) {
        float px = (float)g_hist_x[i] * invres;
        if (px > 0.0f) ex += (double)(-px * log2f(px));
        float pd = (float)g_hist_d[i] * invres;
        if (pd > 0.0f) ed += (double)(-pd * log2f(pd));
    }
    red[t] = ex;
    __syncthreads();
    for (int sft = 128; sft; sft >>= 1) {
        if (t < sft) red[t] += red[t + sft];
        __syncthreads();
    }
    double entx = red[0];
    __syncthreads();
    red[t] = ed;
    __syncthreads();
    for (int sft = 128; sft; sft >>= 1) {
        if (t < sft) red[t] += red[t + sft];
        __syncthreads();
    }
    double entd = red[0];
    if (t == 0) {
        double mean = g_sumsq / 50331648.0;   // 16*3*65536*16
        out[0] = 255.0f * (float)sqrt(mean);
        out[1] = (float)(entx / 384.0);       // 8 * nch, nch=48
        out[2] = (float)(entd / 384.0);
    }
}

extern "C" void kernel_launch(void* const* d_in, const int* in_sizes, int n_in,
                              void* d_out, int out_size) {
    const float* x  = (const float*)d_in[0];
    const float* W0 = (const float*)d_in[1];
    const float* b0 = (const float*)d_in[2];
    const float* W1 = (const float*)d_in[3];
    const float* b1 = (const float*)d_in[4];
    const float* W2 = (const float*)d_in[5];
    const float* b2 = (const float*)d_in[6];
    const float* W3 = (const float*)d_in[7];
    const float* b3 = (const float*)d_in[8];

    codec_zero<<<NBC, 256>>>();
    codec_main<<<NBC * CHUNKS, TPB>>>(x, W0, b0, W1, b1, W2, b2, W3, b3);
    codec_final<<<1, 256>>>((float*)d_out);
}